// round 9
// baseline (speedup 1.0000x reference)
#include <cuda_runtime.h>
#include <math.h>

#define C_CH   128
#define SPA    4096
#define BATCH  2
#define HEADS  4
#define DHEAD  32
#define GROUPS 32
#define CPG    4
#define HTOT   128
#define QKV_R  384
#define EPSV   1e-5f

#define NC     8                 // split-K chunks over keys
#define CHUNK  (SPA / NC)        // 512 keys per chunk

typedef unsigned long long ull;

// Scratch (device globals: allocation-free per harness rules)
__device__ float g_qkv [BATCH * QKV_R * SPA];
__device__ float g_ao  [BATCH * HTOT * SPA];
__device__ float g_mean[BATCH * GROUPS];
__device__ float g_rstd[BATCH * GROUPS];
__device__ float g_pacc[BATCH * HEADS * NC * DHEAD * SPA];
__device__ float g_pm  [BATCH * HEADS * NC * SPA];
__device__ float g_pl  [BATCH * HEADS * NC * SPA];

// ---- Blackwell packed f32x2 helpers ---------------------------------------
__device__ __forceinline__ void ffma2(ull& d, ull a, ull b) {
    asm("fma.rn.f32x2 %0, %1, %2, %0;" : "+l"(d) : "l"(a), "l"(b));
}
__device__ __forceinline__ ull fadd2(ull a, ull b) {
    ull r; asm("add.rn.f32x2 %0, %1, %2;" : "=l"(r) : "l"(a), "l"(b)); return r;
}
__device__ __forceinline__ ull fmul2(ull a, ull b) {
    ull r; asm("mul.rn.f32x2 %0, %1, %2;" : "=l"(r) : "l"(a), "l"(b)); return r;
}
__device__ __forceinline__ ull pack2(float x, float y) {
    ull r; asm("mov.b64 %0, {%1, %2};" : "=l"(r) : "f"(x), "f"(y)); return r;
}
__device__ __forceinline__ float2 unpack2(ull v) {
    float lo, hi; asm("mov.b64 {%0, %1}, %2;" : "=f"(lo), "=f"(hi) : "l"(v));
    return make_float2(lo, hi);
}
__device__ __forceinline__ float ex2(float x) {   // MUFU (cold paths only)
    float r; asm("ex2.approx.ftz.f32 %0, %1;" : "=f"(r) : "f"(x)); return r;
}

// FMA-pipe exp2: no MUFU, no F2I/I2F. Valid for x <= ~30 (we clamp below).
// round via magic constant; exponent via IMAD on reinterpreted bits;
// degree-5 Taylor for 2^r on [-0.5, 0.5] (rel err ~2e-6).
__device__ __forceinline__ float fex2(float x) {
    x = fmaxf(x, -120.0f);
    float t = x + 12582912.0f;            // 1.5 * 2^23: mantissa holds round(x)
    float fi = t - 12582912.0f;           // round(x) as float
    float r = x - fi;                     // [-0.5, 0.5]
    int ib = __float_as_int(t);
    float s = __int_as_float((ib << 23) + (127 << 23));   // 2^round(x)
    float p = 0.0013333558f;
    p = fmaf(p, r, 0.0096181291f);
    p = fmaf(p, r, 0.0555041087f);
    p = fmaf(p, r, 0.2402265069f);
    p = fmaf(p, r, 0.6931471806f);
    p = fmaf(p, r, 1.0f);
    return s * p;
}

// ---------------------------------------------------------------------------
// 1) GroupNorm statistics
// ---------------------------------------------------------------------------
__global__ __launch_bounds__(256) void gn_stats(const float* __restrict__ x) {
    int bg = blockIdx.x;
    const float* p = x + (size_t)bg * (CPG * SPA);
    float s1 = 0.f, s2 = 0.f;
    for (int i = threadIdx.x; i < CPG * SPA; i += 256) {
        float v = p[i];
        s1 += v; s2 += v * v;
    }
    __shared__ float r1[8], r2[8];
    #pragma unroll
    for (int o = 16; o; o >>= 1) {
        s1 += __shfl_down_sync(0xffffffffu, s1, o);
        s2 += __shfl_down_sync(0xffffffffu, s2, o);
    }
    int w = threadIdx.x >> 5, l = threadIdx.x & 31;
    if (l == 0) { r1[w] = s1; r2[w] = s2; }
    __syncthreads();
    if (w == 0) {
        s1 = (l < 8) ? r1[l] : 0.f;
        s2 = (l < 8) ? r2[l] : 0.f;
        #pragma unroll
        for (int o = 4; o; o >>= 1) {
            s1 += __shfl_down_sync(0xffffffffu, s1, o);
            s2 += __shfl_down_sync(0xffffffffu, s2, o);
        }
        if (l == 0) {
            const float invN = 1.0f / (CPG * SPA);
            float mean = s1 * invN;
            float var  = s2 * invN - mean * mean;
            g_mean[bg] = mean;
            g_rstd[bg] = rsqrtf(var + EPSV);
        }
    }
}

// ---------------------------------------------------------------------------
// 2) QKV GEMM with fused GroupNorm on the activation load
// ---------------------------------------------------------------------------
#define BM 64
#define BN 64
#define BK 32

__global__ __launch_bounds__(256) void qkv_gemm(const float* __restrict__ x,
                                                const float* __restrict__ w,
                                                const float* __restrict__ gamma,
                                                const float* __restrict__ beta) {
    int b  = blockIdx.z;
    int m0 = blockIdx.y * BM;
    int n0 = blockIdx.x * BN;
    __shared__ float As[BM * BK];
    __shared__ float Bs[BK * BN];
    int tid = threadIdx.x;
    int tx = tid & 15, ty = tid >> 4;
    float acc[4][4] = {};
    const float* xb = x + (size_t)b * C_CH * SPA;

    for (int k0 = 0; k0 < C_CH; k0 += BK) {
        for (int i = tid; i < BM * BK; i += 256) {
            int row = i / BK, col = i % BK;
            As[i] = w[(size_t)(m0 + row) * C_CH + k0 + col];
        }
        for (int i = tid; i < BK * BN; i += 256) {
            int kk = i / BN, j = i % BN;
            int c = k0 + kk;
            int g = c >> 2;
            float mv = g_mean[b * GROUPS + g];
            float rs = g_rstd[b * GROUPS + g];
            float v = xb[(size_t)c * SPA + n0 + j];
            Bs[i] = (v - mv) * rs * gamma[c] + beta[c];
        }
        __syncthreads();
        #pragma unroll
        for (int kk = 0; kk < BK; kk++) {
            float a[4], bb[4];
            #pragma unroll
            for (int i = 0; i < 4; i++) a[i] = As[(ty * 4 + i) * BK + kk];
            #pragma unroll
            for (int j = 0; j < 4; j++) bb[j] = Bs[kk * BN + tx * 4 + j];
            #pragma unroll
            for (int i = 0; i < 4; i++)
                #pragma unroll
                for (int j = 0; j < 4; j++) acc[i][j] += a[i] * bb[j];
        }
        __syncthreads();
    }
    float* outb = g_qkv + (size_t)b * QKV_R * SPA;
    #pragma unroll
    for (int i = 0; i < 4; i++)
        #pragma unroll
        for (int j = 0; j < 4; j++)
            outb[(size_t)(m0 + ty * 4 + i) * SPA + n0 + tx * 4 + j] = acc[i][j];
}

// ---------------------------------------------------------------------------
// 3a) Flash attention partial: 2 queries/thread, 4-key batches with phase
//     separation. Softmax in log2 domain with FMA-pipe polynomial exp2
//     (MUFU was the binding pipe at 134M ex2 -> ~430us floor; now removed).
//     Grid: (16, HEADS*NC=32, 2) = 1024 blocks of 128 threads.
// ---------------------------------------------------------------------------
#define TQ 256
#define TJ 64
#define KROW 36   // padded row: 9 float4 (144 B)

__global__ __launch_bounds__(128) void attn_partial() {
    int qt = blockIdx.x;
    int nc = blockIdx.y;                 // n*NC + chunk
    int b  = blockIdx.z;
    int n  = nc >> 3, c = nc & (NC - 1);
    int t  = threadIdx.x;

    __shared__ __align__(16) float smem_buf[2 * TJ * KROW];   // 18432 B
    float* sk = smem_buf;
    float* sv = smem_buf + TJ * KROW;

    const float* qkv_b = g_qkv + (size_t)b * QKV_R * SPA;
    const float* qptr = qkv_b + (size_t)(n * DHEAD) * SPA;
    const float* kptr = qkv_b + (size_t)(HTOT + n * DHEAD) * SPA;
    const float* vptr = qkv_b + (size_t)(2 * HTOT + n * DHEAD) * SPA;
    int s0 = qt * TQ;

    // scale * log2(e): softmax in log2 domain
    const float scale2 = 0.17677669529663687f * 1.4426950408889634f;
    ull qA[16], qB[16];
    #pragma unroll
    for (int h = 0; h < 2; h++) {
        __syncthreads();
        for (int i = t; i < 128 * DHEAD; i += 128) {
            int d = i >> 7, sl = i & 127;
            smem_buf[sl * 33 + d] = qptr[(size_t)d * SPA + s0 + h * 128 + sl];
        }
        __syncthreads();
        if (h == 0) {
            #pragma unroll
            for (int i = 0; i < 16; i++)
                qA[i] = pack2(smem_buf[t * 33 + 2 * i] * scale2,
                              smem_buf[t * 33 + 2 * i + 1] * scale2);
        } else {
            #pragma unroll
            for (int i = 0; i < 16; i++)
                qB[i] = pack2(smem_buf[t * 33 + 2 * i] * scale2,
                              smem_buf[t * 33 + 2 * i + 1] * scale2);
        }
    }
    __syncthreads();

    float mA = -1e30f, lA = 0.f, mB = -1e30f, lB = 0.f;
    ull accA[16], accB[16];
    #pragma unroll
    for (int i = 0; i < 16; i++) { accA[i] = 0ull; accB[i] = 0ull; }

    int jbeg = c * CHUNK, jend = jbeg + CHUNK;
    for (int j0 = jbeg; j0 < jend; j0 += TJ) {
        // fill K/V tile: coalesced LDG.32 x4, conflict-free STS.128
        for (int i = t; i < TJ * 8; i += 128) {
            int j = i & (TJ - 1), d4 = i >> 6;
            const float* kp = kptr + (size_t)(d4 * 4) * SPA + j0 + j;
            float4 kk;
            kk.x = kp[0]; kk.y = kp[SPA]; kk.z = kp[2 * SPA]; kk.w = kp[3 * SPA];
            *(float4*)&sk[j * KROW + d4 * 4] = kk;
            const float* vp = vptr + (size_t)(d4 * 4) * SPA + j0 + j;
            float4 vv;
            vv.x = vp[0]; vv.y = vp[SPA]; vv.z = vp[2 * SPA]; vv.w = vp[3 * SPA];
            *(float4*)&sv[j * KROW + d4 * 4] = vv;
        }
        __syncthreads();

        #pragma unroll 1
        for (int jb = 0; jb < TJ; jb += 4) {
            // ---- Phase 1: 8 independent score dots (4 keys x 2 queries) ----
            float scA4[4], scB4[4];
            #pragma unroll
            for (int jj = 0; jj < 4; jj++) {
                const ulonglong2* kr = (const ulonglong2*)&sk[(jb + jj) * KROW];
                ull a0 = 0, a1 = 0, b0 = 0, b1 = 0;
                #pragma unroll
                for (int g = 0; g < 8; g += 2) {
                    ulonglong2 k0 = kr[g], k1 = kr[g + 1];
                    ffma2(a0, qA[2 * g + 0], k0.x);
                    ffma2(a1, qA[2 * g + 1], k0.y);
                    ffma2(a0, qA[2 * g + 2], k1.x);
                    ffma2(a1, qA[2 * g + 3], k1.y);
                    ffma2(b0, qB[2 * g + 0], k0.x);
                    ffma2(b1, qB[2 * g + 1], k0.y);
                    ffma2(b0, qB[2 * g + 2], k1.x);
                    ffma2(b1, qB[2 * g + 3], k1.y);
                }
                a0 = fadd2(a0, a1);
                b0 = fadd2(b0, b1);
                float2 da = unpack2(a0), db = unpack2(b0);
                scA4[jj] = da.x + da.y;
                scB4[jj] = db.x + db.y;
            }

            // ---- Phase 2: batched max update + 8 FMA-pipe exp2 ----
            float bmA = fmaxf(fmaxf(scA4[0], scA4[1]), fmaxf(scA4[2], scA4[3]));
            float bmB = fmaxf(fmaxf(scB4[0], scB4[1]), fmaxf(scB4[2], scB4[3]));
            if (bmA > mA) {                      // rare after warmup
                float corr = fex2(mA - bmA);
                ull cc = pack2(corr, corr);
                lA *= corr;
                #pragma unroll
                for (int i = 0; i < 16; i++) accA[i] = fmul2(accA[i], cc);
                mA = bmA;
            }
            if (bmB > mB) {
                float corr = fex2(mB - bmB);
                ull cc = pack2(corr, corr);
                lB *= corr;
                #pragma unroll
                for (int i = 0; i < 16; i++) accB[i] = fmul2(accB[i], cc);
                mB = bmB;
            }
            float pA4[4], pB4[4];
            #pragma unroll
            for (int jj = 0; jj < 4; jj++) {
                pA4[jj] = fex2(scA4[jj] - mA);
                pB4[jj] = fex2(scB4[jj] - mB);
            }
            lA += (pA4[0] + pA4[1]) + (pA4[2] + pA4[3]);
            lB += (pB4[0] + pB4[1]) + (pB4[2] + pB4[3]);

            // ---- Phase 3: PV accumulate (256 independent ffma2) ----
            #pragma unroll
            for (int jj = 0; jj < 4; jj++) {
                const ulonglong2* vr = (const ulonglong2*)&sv[(jb + jj) * KROW];
                ull ppA = pack2(pA4[jj], pA4[jj]);
                ull ppB = pack2(pB4[jj], pB4[jj]);
                #pragma unroll
                for (int g = 0; g < 8; g++) {
                    ulonglong2 vv = vr[g];
                    ffma2(accA[2 * g + 0], ppA, vv.x);
                    ffma2(accA[2 * g + 1], ppA, vv.y);
                    ffma2(accB[2 * g + 0], ppB, vv.x);
                    ffma2(accB[2 * g + 1], ppB, vv.y);
                }
            }
        }
        __syncthreads();
    }

    // write partials (unnormalized); m is in log2 domain — combine matches
    size_t base = (size_t)(b * HEADS + n) * NC + c;
    g_pm[base * SPA + s0 + t]       = mA;
    g_pl[base * SPA + s0 + t]       = lA;
    g_pm[base * SPA + s0 + 128 + t] = mB;
    g_pl[base * SPA + s0 + 128 + t] = lB;
    float* pa = g_pacc + base * (DHEAD * SPA);
    #pragma unroll
    for (int i = 0; i < 16; i++) {
        float2 va = unpack2(accA[i]);
        float2 vb = unpack2(accB[i]);
        pa[(size_t)(2 * i + 0) * SPA + s0 + t]       = va.x;
        pa[(size_t)(2 * i + 1) * SPA + s0 + t]       = va.y;
        pa[(size_t)(2 * i + 0) * SPA + s0 + 128 + t] = vb.x;
        pa[(size_t)(2 * i + 1) * SPA + s0 + 128 + t] = vb.y;
    }
}

// ---------------------------------------------------------------------------
// 3b) Combine split-K partials -> g_ao (m/l log2-domain; MUFU ex2 fine here)
// ---------------------------------------------------------------------------
__global__ __launch_bounds__(256) void attn_combine() {
    int t = threadIdx.x;
    int s = blockIdx.x * 256 + t;
    int yb = blockIdx.y;
    int n = yb >> 2, dbase = (yb & 3) * 8;
    int b = blockIdx.z;
    size_t base = (size_t)(b * HEADS + n) * NC;

    float pm[NC];
    float m = -1e30f;
    #pragma unroll
    for (int c = 0; c < NC; c++) {
        pm[c] = g_pm[(base + c) * SPA + s];
        m = fmaxf(m, pm[c]);
    }
    float wgt[NC];
    float L = 0.f;
    #pragma unroll
    for (int c = 0; c < NC; c++) {
        wgt[c] = ex2(fmaxf(pm[c] - m, -120.0f));
        L += g_pl[(base + c) * SPA + s] * wgt[c];
    }
    float invL = 1.0f / L;
    #pragma unroll
    for (int c = 0; c < NC; c++) wgt[c] *= invL;

    float* ao = g_ao + ((size_t)b * HTOT + n * DHEAD) * SPA;
    #pragma unroll
    for (int dd = 0; dd < 8; dd++) {
        int d = dbase + dd;
        float a = 0.f;
        #pragma unroll
        for (int c = 0; c < NC; c++)
            a += g_pacc[((base + c) * DHEAD + d) * SPA + s] * wgt[c];
        ao[(size_t)d * SPA + s] = a;
    }
}

// ---------------------------------------------------------------------------
// 4) Output projection
// ---------------------------------------------------------------------------
__global__ __launch_bounds__(256) void out_gemm(const float* __restrict__ w,
                                                const float* __restrict__ bias,
                                                float* __restrict__ y) {
    int b  = blockIdx.z;
    int m0 = blockIdx.y * BM;
    int n0 = blockIdx.x * BN;
    __shared__ float As[BM * BK];
    __shared__ float Bs[BK * BN];
    int tid = threadIdx.x;
    int tx = tid & 15, ty = tid >> 4;
    float acc[4][4] = {};
    const float* ab = g_ao + (size_t)b * HTOT * SPA;

    for (int k0 = 0; k0 < HTOT; k0 += BK) {
        for (int i = tid; i < BM * BK; i += 256) {
            int row = i / BK, col = i % BK;
            As[i] = w[(size_t)(m0 + row) * HTOT + k0 + col];
        }
        for (int i = tid; i < BK * BN; i += 256) {
            int kk = i / BN, j = i % BN;
            Bs[i] = ab[(size_t)(k0 + kk) * SPA + n0 + j];
        }
        __syncthreads();
        #pragma unroll
        for (int kk = 0; kk < BK; kk++) {
            float a[4], bb[4];
            #pragma unroll
            for (int i = 0; i < 4; i++) a[i] = As[(ty * 4 + i) * BK + kk];
            #pragma unroll
            for (int j = 0; j < 4; j++) bb[j] = Bs[kk * BN + tx * 4 + j];
            #pragma unroll
            for (int i = 0; i < 4; i++)
                #pragma unroll
                for (int j = 0; j < 4; j++) acc[i][j] += a[i] * bb[j];
        }
        __syncthreads();
    }
    #pragma unroll
    for (int i = 0; i < 4; i++) {
        float bv = bias[m0 + ty * 4 + i];
        #pragma unroll
        for (int j = 0; j < 4; j++)
            y[(size_t)(b * C_CH + m0 + ty * 4 + i) * SPA + n0 + tx * 4 + j] =
                acc[i][j] + bv;
    }
}

// ---------------------------------------------------------------------------
extern "C" void kernel_launch(void* const* d_in, const int* in_sizes, int n_in,
                              void* d_out, int out_size) {
    const float* x     = (const float*)d_in[0];
    const float* gamma = (const float*)d_in[1];
    const float* beta  = (const float*)d_in[2];
    const float* w_qkv = (const float*)d_in[3];
    const float* w_out = (const float*)d_in[4];
    const float* b_out = (const float*)d_in[5];
    float* y = (float*)d_out;

    gn_stats<<<BATCH * GROUPS, 256>>>(x);
    qkv_gemm<<<dim3(SPA / BN, QKV_R / BM, BATCH), 256>>>(x, w_qkv, gamma, beta);
    attn_partial<<<dim3(SPA / TQ, HEADS * NC, BATCH), 128>>>();
    attn_combine<<<dim3(SPA / 256, HEADS * 4, BATCH), 256>>>();
    out_gemm<<<dim3(SPA / BN, C_CH / BM, BATCH), 256>>>(w_out, b_out, y);
}

// round 11
// speedup vs baseline: 1.6304x; 1.6304x over previous
#include <cuda_runtime.h>
#include <math.h>

#define C_CH   128
#define SPA    4096
#define BATCH  2
#define HEADS  4
#define DHEAD  32
#define GROUPS 32
#define CPG    4
#define HTOT   128
#define QKV_R  384
#define EPSV   1e-5f

#define NC     8                 // split-K chunks over keys
#define CHUNK  (SPA / NC)        // 512 keys per chunk
#define MT     64                // queries per block
#define KT     32                // keys per inner tile

// Scratch (device globals: allocation-free per harness rules)
__device__ float g_qkv [BATCH * QKV_R * SPA];
__device__ float g_ao  [BATCH * HTOT * SPA];
__device__ float g_mean[BATCH * GROUPS];
__device__ float g_rstd[BATCH * GROUPS];
__device__ float g_pacc[BATCH * HEADS * NC * DHEAD * SPA];
__device__ float g_pm  [BATCH * HEADS * NC * SPA];
__device__ float g_pl  [BATCH * HEADS * NC * SPA];

__device__ __forceinline__ float ex2(float x) {   // MUFU (cheap: ~27us chip floor)
    float r; asm("ex2.approx.ftz.f32 %0, %1;" : "=f"(r) : "f"(x)); return r;
}
__device__ __forceinline__ unsigned to_tf32(float f) {
    unsigned u; asm("cvt.rna.tf32.f32 %0, %1;" : "=r"(u) : "f"(f)); return u;
}
// D += A(16x8,row) * B(8x8,col) ; tf32 operands, f32 accum
__device__ __forceinline__ void mma_tf32(float* c, const unsigned* a,
                                         unsigned b0, unsigned b1) {
    asm volatile(
        "mma.sync.aligned.m16n8k8.row.col.f32.tf32.tf32.f32 "
        "{%0,%1,%2,%3}, {%4,%5,%6,%7}, {%8,%9}, {%0,%1,%2,%3};"
        : "+f"(c[0]), "+f"(c[1]), "+f"(c[2]), "+f"(c[3])
        : "r"(a[0]), "r"(a[1]), "r"(a[2]), "r"(a[3]), "r"(b0), "r"(b1));
}

// ---------------------------------------------------------------------------
// 1) GroupNorm statistics
// ---------------------------------------------------------------------------
__global__ __launch_bounds__(256) void gn_stats(const float* __restrict__ x) {
    int bg = blockIdx.x;
    const float* p = x + (size_t)bg * (CPG * SPA);
    float s1 = 0.f, s2 = 0.f;
    for (int i = threadIdx.x; i < CPG * SPA; i += 256) {
        float v = p[i];
        s1 += v; s2 += v * v;
    }
    __shared__ float r1[8], r2[8];
    #pragma unroll
    for (int o = 16; o; o >>= 1) {
        s1 += __shfl_down_sync(0xffffffffu, s1, o);
        s2 += __shfl_down_sync(0xffffffffu, s2, o);
    }
    int w = threadIdx.x >> 5, l = threadIdx.x & 31;
    if (l == 0) { r1[w] = s1; r2[w] = s2; }
    __syncthreads();
    if (w == 0) {
        s1 = (l < 8) ? r1[l] : 0.f;
        s2 = (l < 8) ? r2[l] : 0.f;
        #pragma unroll
        for (int o = 4; o; o >>= 1) {
            s1 += __shfl_down_sync(0xffffffffu, s1, o);
            s2 += __shfl_down_sync(0xffffffffu, s2, o);
        }
        if (l == 0) {
            const float invN = 1.0f / (CPG * SPA);
            float mean = s1 * invN;
            float var  = s2 * invN - mean * mean;
            g_mean[bg] = mean;
            g_rstd[bg] = rsqrtf(var + EPSV);
        }
    }
}

// ---------------------------------------------------------------------------
// 2) QKV GEMM with fused GroupNorm on the activation load
// ---------------------------------------------------------------------------
#define BM 64
#define BN 64
#define BK 32

__global__ __launch_bounds__(256) void qkv_gemm(const float* __restrict__ x,
                                                const float* __restrict__ w,
                                                const float* __restrict__ gamma,
                                                const float* __restrict__ beta) {
    int b  = blockIdx.z;
    int m0 = blockIdx.y * BM;
    int n0 = blockIdx.x * BN;
    __shared__ float As[BM * BK];
    __shared__ float Bs[BK * BN];
    int tid = threadIdx.x;
    int tx = tid & 15, ty = tid >> 4;
    float acc[4][4] = {};
    const float* xb = x + (size_t)b * C_CH * SPA;

    for (int k0 = 0; k0 < C_CH; k0 += BK) {
        for (int i = tid; i < BM * BK; i += 256) {
            int row = i / BK, col = i % BK;
            As[i] = w[(size_t)(m0 + row) * C_CH + k0 + col];
        }
        for (int i = tid; i < BK * BN; i += 256) {
            int kk = i / BN, j = i % BN;
            int c = k0 + kk;
            int g = c >> 2;
            float mv = g_mean[b * GROUPS + g];
            float rs = g_rstd[b * GROUPS + g];
            float v = xb[(size_t)c * SPA + n0 + j];
            Bs[i] = (v - mv) * rs * gamma[c] + beta[c];
        }
        __syncthreads();
        #pragma unroll
        for (int kk = 0; kk < BK; kk++) {
            float a[4], bb[4];
            #pragma unroll
            for (int i = 0; i < 4; i++) a[i] = As[(ty * 4 + i) * BK + kk];
            #pragma unroll
            for (int j = 0; j < 4; j++) bb[j] = Bs[kk * BN + tx * 4 + j];
            #pragma unroll
            for (int i = 0; i < 4; i++)
                #pragma unroll
                for (int j = 0; j < 4; j++) acc[i][j] += a[i] * bb[j];
        }
        __syncthreads();
    }
    float* outb = g_qkv + (size_t)b * QKV_R * SPA;
    #pragma unroll
    for (int i = 0; i < 4; i++)
        #pragma unroll
        for (int j = 0; j < 4; j++)
            outb[(size_t)(m0 + ty * 4 + i) * SPA + n0 + tx * 4 + j] = acc[i][j];
}

// ---------------------------------------------------------------------------
// 3a) Flash attention partial — TENSOR CORE (tf32 mma.sync m16n8k8).
//     Block: 128 thr (4 warps), 64 queries (16 rows/warp), KT=32 key tiles.
//     QK^T in 3xTF32 (hi/lo split: near-fp32 scores). PV single tf32.
//     Softmax log2-domain on fragments, quad-shfl row reductions, MUFU ex2.
//     Grid: (64, HEADS*NC=32, 2) = 4096 blocks.
// ---------------------------------------------------------------------------
__global__ __launch_bounds__(128) void attn_partial() {
    int qt = blockIdx.x;
    int yc = blockIdx.y;
    int b  = blockIdx.z;
    int n  = yc >> 3, c = yc & (NC - 1);
    int t  = threadIdx.x;
    int w  = t >> 5, lane = t & 31;
    int g  = lane >> 2, tg = lane & 3;     // mma fragment coords
    int r0 = w * 16 + g;                   // this thread's first q-row (of 2)

    // smem: s_buf = Q stage [32][72] f32, then reused as P tile [64][36] tf32
    __shared__ __align__(16) unsigned s_buf[2304];
    __shared__ __align__(16) unsigned s_kh[KT * 36];
    __shared__ __align__(16) unsigned s_kl[KT * 36];
    __shared__ __align__(16) unsigned s_v [KT * 36];

    const float* qkv_b = g_qkv + (size_t)b * QKV_R * SPA;
    const float* qptr = qkv_b + (size_t)(n * DHEAD) * SPA;
    const float* kptr = qkv_b + (size_t)(HTOT + n * DHEAD) * SPA;
    const float* vptr = qkv_b + (size_t)(2 * HTOT + n * DHEAD) * SPA;
    int s0 = qt * MT;

    const float scale2 = 0.17677669529663687f * 1.4426950408889634f; // /sqrt(32)*log2e

    // ---- stage Q (scaled f32) as [d][72], coalesced + conflict-free ----
    float* sQ = (float*)s_buf;
    for (int idx = t; idx < MT * DHEAD; idx += 128) {
        int d = idx >> 6, row = idx & 63;
        sQ[d * 72 + row] = qptr[(size_t)d * SPA + s0 + row] * scale2;
    }
    __syncthreads();

    // ---- extract Q fragments, split hi/lo tf32 (for 3xTF32 QK) ----
    // a0:[r0][d], a1:[r0+8][d], a2:[r0][d+4], a3:[r0+8][d+4], d = ks*8+tg
    unsigned qh[4][4], ql[4][4];
    #pragma unroll
    for (int ks = 0; ks < 4; ks++) {
        int d = ks * 8 + tg;
        float v0 = sQ[d * 72 + r0];
        float v1 = sQ[d * 72 + r0 + 8];
        float v2 = sQ[(d + 4) * 72 + r0];
        float v3 = sQ[(d + 4) * 72 + r0 + 8];
        qh[ks][0] = to_tf32(v0); ql[ks][0] = to_tf32(v0 - __uint_as_float(qh[ks][0]));
        qh[ks][1] = to_tf32(v1); ql[ks][1] = to_tf32(v1 - __uint_as_float(qh[ks][1]));
        qh[ks][2] = to_tf32(v2); ql[ks][2] = to_tf32(v2 - __uint_as_float(qh[ks][2]));
        qh[ks][3] = to_tf32(v3); ql[ks][3] = to_tf32(v3 - __uint_as_float(qh[ks][3]));
    }
    __syncthreads();                       // s_buf now becomes P tile
    unsigned* sP = s_buf;                  // [64][36] tf32 bits

    float m0 = -1e30f, m1 = -1e30f, l0 = 0.f, l1 = 0.f;
    float of[4][4] = {};                   // O accum fragments [ntile(d)][4]

    int jbeg = c * CHUNK, jend = jbeg + CHUNK;
    for (int j0 = jbeg; j0 < jend; j0 += KT) {
        __syncthreads();
        // ---- fill K (hi/lo tf32) and V (tf32), conflict-free STS ----
        #pragma unroll
        for (int k = 0; k < 8; k++) {
            int j = t >> 2, d = (t & 3) + 4 * k;
            float kv = kptr[(size_t)d * SPA + j0 + j];
            unsigned h = to_tf32(kv);
            s_kh[j * 36 + d] = h;
            s_kl[j * 36 + d] = to_tf32(kv - __uint_as_float(h));
            s_v [j * 36 + d] = to_tf32(vptr[(size_t)d * SPA + j0 + j]);
        }
        __syncthreads();

        // ---- S = Q @ K^T via 3xTF32: QhKh + QhKl + QlKh ----
        float sc[4][4] = {};
        #pragma unroll
        for (int ks = 0; ks < 4; ks++) {
            #pragma unroll
            for (int nt = 0; nt < 4; nt++) {
                int kr = (nt * 8 + g) * 36 + ks * 8 + tg;  // key row, d col
                unsigned bh0 = s_kh[kr], bh1 = s_kh[kr + 4];
                unsigned bl0 = s_kl[kr], bl1 = s_kl[kr + 4];
                mma_tf32(sc[nt], qh[ks], bh0, bh1);
                mma_tf32(sc[nt], qh[ks], bl0, bl1);
                mma_tf32(sc[nt], ql[ks], bh0, bh1);
            }
        }

        // ---- softmax (log2 domain) on fragments ----
        float rm0 = fmaxf(fmaxf(sc[0][0], sc[0][1]), fmaxf(sc[1][0], sc[1][1]));
        rm0 = fmaxf(rm0, fmaxf(fmaxf(sc[2][0], sc[2][1]), fmaxf(sc[3][0], sc[3][1])));
        float rm1 = fmaxf(fmaxf(sc[0][2], sc[0][3]), fmaxf(sc[1][2], sc[1][3]));
        rm1 = fmaxf(rm1, fmaxf(fmaxf(sc[2][2], sc[2][3]), fmaxf(sc[3][2], sc[3][3])));
        rm0 = fmaxf(rm0, __shfl_xor_sync(0xffffffffu, rm0, 1));
        rm0 = fmaxf(rm0, __shfl_xor_sync(0xffffffffu, rm0, 2));
        rm1 = fmaxf(rm1, __shfl_xor_sync(0xffffffffu, rm1, 1));
        rm1 = fmaxf(rm1, __shfl_xor_sync(0xffffffffu, rm1, 2));
        float nm0 = fmaxf(m0, rm0), nm1 = fmaxf(m1, rm1);
        float c0 = ex2(m0 - nm0), c1 = ex2(m1 - nm1);
        l0 *= c0; l1 *= c1;
        #pragma unroll
        for (int nt = 0; nt < 4; nt++) {
            of[nt][0] *= c0; of[nt][1] *= c0;
            of[nt][2] *= c1; of[nt][3] *= c1;
        }
        m0 = nm0; m1 = nm1;

        float ps0 = 0.f, ps1 = 0.f;
        #pragma unroll
        for (int nt = 0; nt < 4; nt++) {
            float p00 = ex2(sc[nt][0] - m0);
            float p01 = ex2(sc[nt][1] - m0);
            float p10 = ex2(sc[nt][2] - m1);
            float p11 = ex2(sc[nt][3] - m1);
            ps0 += p00 + p01; ps1 += p10 + p11;
            int col = nt * 8 + 2 * tg;
            sP[r0 * 36 + col]           = to_tf32(p00);
            sP[r0 * 36 + col + 1]       = to_tf32(p01);
            sP[(r0 + 8) * 36 + col]     = to_tf32(p10);
            sP[(r0 + 8) * 36 + col + 1] = to_tf32(p11);
        }
        l0 += ps0; l1 += ps1;
        __syncwarp();                      // warp reads only its own P rows

        // ---- O += P @ V (single tf32; P,V quantization ~2e-4 rel) ----
        #pragma unroll
        for (int ks = 0; ks < 4; ks++) {
            unsigned af[4];
            af[0] = sP[r0 * 36 + ks * 8 + tg];
            af[1] = sP[(r0 + 8) * 36 + ks * 8 + tg];
            af[2] = sP[r0 * 36 + ks * 8 + tg + 4];
            af[3] = sP[(r0 + 8) * 36 + ks * 8 + tg + 4];
            #pragma unroll
            for (int nt = 0; nt < 4; nt++) {
                unsigned b0 = s_v[(ks * 8 + tg) * 36 + nt * 8 + g];
                unsigned b1 = s_v[(ks * 8 + tg + 4) * 36 + nt * 8 + g];
                mma_tf32(of[nt], af, b0, b1);
            }
        }
    }

    // ---- finalize l (quad reduce) and write partials ----
    l0 += __shfl_xor_sync(0xffffffffu, l0, 1);
    l0 += __shfl_xor_sync(0xffffffffu, l0, 2);
    l1 += __shfl_xor_sync(0xffffffffu, l1, 1);
    l1 += __shfl_xor_sync(0xffffffffu, l1, 2);

    size_t base = (size_t)(b * HEADS + n) * NC + c;
    if (tg == 0) {
        g_pm[base * SPA + s0 + r0]     = m0;
        g_pl[base * SPA + s0 + r0]     = l0;
        g_pm[base * SPA + s0 + r0 + 8] = m1;
        g_pl[base * SPA + s0 + r0 + 8] = l1;
    }
    float* pa = g_pacc + base * (DHEAD * SPA);
    #pragma unroll
    for (int nt = 0; nt < 4; nt++) {
        int d0 = nt * 8 + 2 * tg;
        pa[(size_t)d0 * SPA + s0 + r0]           = of[nt][0];
        pa[(size_t)(d0 + 1) * SPA + s0 + r0]     = of[nt][1];
        pa[(size_t)d0 * SPA + s0 + r0 + 8]       = of[nt][2];
        pa[(size_t)(d0 + 1) * SPA + s0 + r0 + 8] = of[nt][3];
    }
}

// ---------------------------------------------------------------------------
// 3b) Combine split-K partials -> g_ao (m/l log2-domain)
// ---------------------------------------------------------------------------
__global__ __launch_bounds__(256) void attn_combine() {
    int t = threadIdx.x;
    int s = blockIdx.x * 256 + t;
    int yb = blockIdx.y;
    int n = yb >> 2, dbase = (yb & 3) * 8;
    int b = blockIdx.z;
    size_t base = (size_t)(b * HEADS + n) * NC;

    float pm[NC];
    float m = -1e30f;
    #pragma unroll
    for (int c = 0; c < NC; c++) {
        pm[c] = g_pm[(base + c) * SPA + s];
        m = fmaxf(m, pm[c]);
    }
    float wgt[NC];
    float L = 0.f;
    #pragma unroll
    for (int c = 0; c < NC; c++) {
        wgt[c] = ex2(fmaxf(pm[c] - m, -120.0f));
        L += g_pl[(base + c) * SPA + s] * wgt[c];
    }
    float invL = 1.0f / L;
    #pragma unroll
    for (int c = 0; c < NC; c++) wgt[c] *= invL;

    float* ao = g_ao + ((size_t)b * HTOT + n * DHEAD) * SPA;
    #pragma unroll
    for (int dd = 0; dd < 8; dd++) {
        int d = dbase + dd;
        float a = 0.f;
        #pragma unroll
        for (int c = 0; c < NC; c++)
            a += g_pacc[((base + c) * DHEAD + d) * SPA + s] * wgt[c];
        ao[(size_t)d * SPA + s] = a;
    }
}

// ---------------------------------------------------------------------------
// 4) Output projection
// ---------------------------------------------------------------------------
__global__ __launch_bounds__(256) void out_gemm(const float* __restrict__ w,
                                                const float* __restrict__ bias,
                                                float* __restrict__ y) {
    int b  = blockIdx.z;
    int m0 = blockIdx.y * BM;
    int n0 = blockIdx.x * BN;
    __shared__ float As[BM * BK];
    __shared__ float Bs[BK * BN];
    int tid = threadIdx.x;
    int tx = tid & 15, ty = tid >> 4;
    float acc[4][4] = {};
    const float* ab = g_ao + (size_t)b * HTOT * SPA;

    for (int k0 = 0; k0 < HTOT; k0 += BK) {
        for (int i = tid; i < BM * BK; i += 256) {
            int row = i / BK, col = i % BK;
            As[i] = w[(size_t)(m0 + row) * HTOT + k0 + col];
        }
        for (int i = tid; i < BK * BN; i += 256) {
            int kk = i / BN, j = i % BN;
            Bs[i] = ab[(size_t)(k0 + kk) * SPA + n0 + j];
        }
        __syncthreads();
        #pragma unroll
        for (int kk = 0; kk < BK; kk++) {
            float a[4], bb[4];
            #pragma unroll
            for (int i = 0; i < 4; i++) a[i] = As[(ty * 4 + i) * BK + kk];
            #pragma unroll
            for (int j = 0; j < 4; j++) bb[j] = Bs[kk * BN + tx * 4 + j];
            #pragma unroll
            for (int i = 0; i < 4; i++)
                #pragma unroll
                for (int j = 0; j < 4; j++) acc[i][j] += a[i] * bb[j];
        }
        __syncthreads();
    }
    #pragma unroll
    for (int i = 0; i < 4; i++) {
        float bv = bias[m0 + ty * 4 + i];
        #pragma unroll
        for (int j = 0; j < 4; j++)
            y[(size_t)(b * C_CH + m0 + ty * 4 + i) * SPA + n0 + tx * 4 + j] =
                acc[i][j] + bv;
    }
}

// ---------------------------------------------------------------------------
extern "C" void kernel_launch(void* const* d_in, const int* in_sizes, int n_in,
                              void* d_out, int out_size) {
    const float* x     = (const float*)d_in[0];
    const float* gamma = (const float*)d_in[1];
    const float* beta  = (const float*)d_in[2];
    const float* w_qkv = (const float*)d_in[3];
    const float* w_out = (const float*)d_in[4];
    const float* b_out = (const float*)d_in[5];
    float* y = (float*)d_out;

    gn_stats<<<BATCH * GROUPS, 256>>>(x);
    qkv_gemm<<<dim3(SPA / BN, QKV_R / BM, BATCH), 256>>>(x, w_qkv, gamma, beta);
    attn_partial<<<dim3(SPA / MT, HEADS * NC, BATCH), 128>>>();
    attn_combine<<<dim3(SPA / 256, HEADS * 4, BATCH), 256>>>();
    out_gemm<<<dim3(SPA / BN, C_CH / BM, BATCH), 256>>>(w_out, b_out, y);
}